// round 11
// baseline (speedup 1.0000x reference)
#include <cuda_runtime.h>
#include <cstdint>
#include <cstddef>

// Problem constants
#define BB 16
#define CC 256
#define HH 64
#define WW 64
#define HW (HH*WW)
#define DD 4          // max displacement
#define PP 9          // patch = 2d+1

// Tiling
#define TI 4          // rows per block tile
#define KC 8          // channels per staged chunk
#define NCHUNK (CC/KC)
#define XS 64         // x smem row stride (floats) = 16 f4, XOR-swizzled
#define YR (TI + 2*DD)   // 12 y rows per tile
#define YSF 96        // y smem row stride (floats) = 24 f4, XOR-swizzled (closed)

#define NTH 288       // 9 warps; warp w == displacement row di
#define NBUF 2

#define XSZ (KC*TI*XS)      // 2048 floats
#define YSZ (KC*YR*YSF)     // 9216 floats
#define BUFSZ (XSZ+YSZ)     // 11264 floats = 45056 B
#define SMEM_BYTES (NBUF*BUFSZ*4)   // 90112 B; 2 blocks/SM = 176 KB

// Per-row XOR swizzle on 16B (f4) granularity: distinct (bit0,bit2) classes.
__device__ __forceinline__ int swz(int row) {
    return (row & 1) | ((row & 2) << 1);   // {0,1,4,5}
}

__device__ __forceinline__ uint32_t s2u(const void* p) {
    return (uint32_t)__cvta_generic_to_shared(p);
}
__device__ __forceinline__ void cpa16(uint32_t s, const float* g) {
    asm volatile("cp.async.ca.shared.global [%0], [%1], 16;\n" :: "r"(s), "l"(g));
}
__device__ __forceinline__ void cp_commit() {
    asm volatile("cp.async.commit_group;\n");
}

// Stage one 8-channel chunk. 16B jobs, shift/mask index math only.
__device__ __forceinline__ void stage_chunk(float* sb,
                                            const float* __restrict__ xb,
                                            const float* __restrict__ yb,
                                            int c0, int i0, int tid, int vmask)
{
    // x: KC*TI*16 = 512 f4 jobs. phys_f4 = j4 ^ swz(rr)
    for (int idx = tid; idx < KC * TI * 16; idx += NTH) {
        int c  = idx >> 6;
        int rr = (idx >> 4) & 3;
        int j4 = idx & 15;
        uint32_t s = s2u(sb + c * (TI * XS) + rr * XS + ((j4 ^ swz(rr)) << 2));
        cpa16(s, xb + (size_t)(c0 + c) * HW + (i0 + rr) * WW + (j4 << 2));
    }
    // y: YR*KC*16 = 1536 f4 jobs. data occupies logical f4 2..17 (float 8..71);
    // phys_f4 = (j4+2) ^ swz(q)
    for (int idx = tid; idx < YR * KC * 16; idx += NTH) {
        int q  = idx >> 7;          // 0..11
        int c  = (idx >> 4) & 7;
        int j4 = idx & 15;
        if ((vmask >> q) & 1) {
            int gi = i0 + q - DD;
            uint32_t s = s2u(sb + XSZ + c * (YR * YSF) + q * YSF +
                             (((j4 + 2) ^ swz(q & 3)) << 2));
            cpa16(s, yb + (size_t)(c0 + c) * HW + gi * WW + (j4 << 2));
        }
    }
}

// Compute: 8 cols x 9 dj per thread, 72 scalar FFMA per channel, 6 LDS.128.
__device__ __forceinline__ void compute_chunk(const float* sb, float acc[8][PP],
                                              int r, int ry, int q)
{
    const float4* X = reinterpret_cast<const float4*>(sb) + r * (XS / 4);
    const float4* Y = reinterpret_cast<const float4*>(sb + XSZ) + ry * (YSF / 4);
    const int swr = swz(r);
    const int swy = swz(ry & 3);
    const int x0 = (2 * q)     ^ swr;
    const int x1 = (2 * q + 1) ^ swr;
    const int y0 = (2 * q + 1) ^ swy;
    const int y1 = (2 * q + 2) ^ swy;
    const int y2 = (2 * q + 3) ^ swy;
    const int y3 = (2 * q + 4) ^ swy;

    #pragma unroll
    for (int c = 0; c < KC; ++c) {
        float4 a0 = X[c * (TI * XS / 4) + x0];
        float4 a1 = X[c * (TI * XS / 4) + x1];
        float4 b0 = Y[c * (YR * YSF / 4) + y0];
        float4 b1 = Y[c * (YR * YSF / 4) + y1];
        float4 b2 = Y[c * (YR * YSF / 4) + y2];
        float4 b3 = Y[c * (YR * YSF / 4) + y3];

        float xv[8]  = {a0.x, a0.y, a0.z, a0.w, a1.x, a1.y, a1.z, a1.w};
        float yv[16] = {b0.x, b0.y, b0.z, b0.w, b1.x, b1.y, b1.z, b1.w,
                        b2.x, b2.y, b2.z, b2.w, b3.x, b3.y, b3.z, b3.w};
        #pragma unroll
        for (int k = 0; k < 8; ++k)
            #pragma unroll
            for (int d = 0; d < PP; ++d)
                acc[k][d] += xv[k] * yv[k + d];
    }
}

__global__ __launch_bounds__(NTH, 2)
void corr_kernel(const float* __restrict__ x,
                 const float* __restrict__ y,
                 float* __restrict__ out)
{
    extern __shared__ float smem[];   // [NBUF][BUFSZ]

    const int bx   = blockIdx.x;
    const int b    = bx >> 4;
    const int i0   = (bx & 15) * TI;
    const int tid  = threadIdx.x;
    const int di   = tid >> 5;
    const int lane = tid & 31;
    const int r    = lane & 3;
    const int q    = lane >> 2;        // j-segment index, jseg = 8q
    const int ry   = r + di;           // padded y row this thread reads
    const int jseg = q * 8;

    const float* xb = x + (size_t)b * CC * HW;
    const float* yb = y + (size_t)b * CC * HW;

    // Valid-row mask for the y tile (rows i0-4 .. i0+7)
    int vmask = 0;
    #pragma unroll
    for (int qq = 0; qq < YR; ++qq) {
        int gi = i0 + qq - DD;
        if (gi >= 0 && gi < HH) vmask |= (1 << qq);
    }

    // Zero the y regions of both buffers once. Stores only ever touch the
    // phys slots {2..17}^sw of valid rows, so halo slots stay zero.
    {
        const float4 z = make_float4(0.f, 0.f, 0.f, 0.f);
        #pragma unroll
        for (int nb = 0; nb < NBUF; ++nb) {
            float4* yz = reinterpret_cast<float4*>(smem + nb * BUFSZ + XSZ);
            for (int idx = tid; idx < YSZ / 4; idx += NTH) yz[idx] = z;
        }
    }
    __syncthreads();

    float acc[8][PP];
    #pragma unroll
    for (int k = 0; k < 8; ++k)
        #pragma unroll
        for (int d = 0; d < PP; ++d)
            acc[k][d] = 0.0f;

    // Prime
    stage_chunk(smem, xb, yb, 0, i0, tid, vmask);
    cp_commit();

    for (int k = 0; k < NCHUNK; ++k) {
        if (k + 1 < NCHUNK) {
            stage_chunk(smem + ((k + 1) & 1) * BUFSZ, xb, yb,
                        (k + 1) * KC, i0, tid, vmask);
            cp_commit();
            asm volatile("cp.async.wait_group 1;\n");
        } else {
            asm volatile("cp.async.wait_group 0;\n");
        }
        __syncthreads();
        compute_chunk(smem + (k & 1) * BUFSZ, acc, r, ry, q);
        __syncthreads();
    }

    // Write out: out[b, di*9+d, i0+r, jseg..jseg+7]
    const float scale = 1.0f / (float)CC;
    #pragma unroll
    for (int d = 0; d < PP; ++d) {
        int ch = di * PP + d;
        float* o = out + (((size_t)b * (PP * PP) + ch) * HH + (i0 + r)) * WW + jseg;
        float4 v0, v1;
        v0.x = acc[0][d] * scale; v0.y = acc[1][d] * scale;
        v0.z = acc[2][d] * scale; v0.w = acc[3][d] * scale;
        v1.x = acc[4][d] * scale; v1.y = acc[5][d] * scale;
        v1.z = acc[6][d] * scale; v1.w = acc[7][d] * scale;
        reinterpret_cast<float4*>(o)[0] = v0;
        reinterpret_cast<float4*>(o)[1] = v1;
    }
}

extern "C" void kernel_launch(void* const* d_in, const int* in_sizes, int n_in,
                              void* d_out, int out_size)
{
    const float* x = (const float*)d_in[0];
    const float* y = (const float*)d_in[1];
    float* out = (float*)d_out;
    (void)in_sizes; (void)n_in; (void)out_size;

    cudaFuncSetAttribute(corr_kernel,
                         cudaFuncAttributeMaxDynamicSharedMemorySize, SMEM_BYTES);

    dim3 grid(BB * (HH / TI));   // 256 blocks
    dim3 block(NTH);             // 9 warps
    corr_kernel<<<grid, block, SMEM_BYTES>>>(x, y, out);
}